// round 5
// baseline (speedup 1.0000x reference)
#include <cuda_runtime.h>
#include <cuda_bf16.h>

// Problem constants (fixed by the reference setup).
#define BB   256
#define NN   4000
#define GG   50
#define M_TOT (BB * NN)      // 1,024,000 elements
#define TMAX  (BB * GG)      // 12,800 max TPs per threshold
#define NBKT  256

// ----------------------------------------------------------------------------
// Device scratch (static globals — no allocation allowed)
// ----------------------------------------------------------------------------
__device__ unsigned char      g_tp[M_TOT];           // per-element TP bits (bit0: thr .5, bit1: thr .75)
__device__ unsigned long long g_list[2][TMAX];       // compacted TP keys (unordered)
__device__ unsigned long long g_btmp[2][TMAX];       // bucketed (unsorted within bucket)
__device__ unsigned long long g_sorted[2][TMAX];     // fully sorted ascending key
__device__ int g_T[2];                               // TP counts
__device__ int g_bcount[2][NBKT];
__device__ int g_boff[2][NBKT + 1];
__device__ int g_bfill[2][NBKT];
__device__ int g_c[2][TMAX + 1];                     // lower-bound histogram

// ----------------------------------------------------------------------------
// Key construction: ascending key == (conf descending, index ascending).
// Low byte carries the value-based bucket (monotone non-decreasing with key).
// ----------------------------------------------------------------------------
__device__ __forceinline__ unsigned int ford(float f) {
    unsigned int u = __float_as_uint(f);
    return (u & 0x80000000u) ? ~u : (u | 0x80000000u);   // ascending float order
}
__device__ __forceinline__ int bucket_of(float conf) {
    int bi = (int)(conf * 256.0f);
    bi = bi < 0 ? 0 : (bi > 255 ? 255 : bi);
    return 255 - bi;                                      // higher conf -> smaller bucket
}
__device__ __forceinline__ unsigned long long make_key(float conf, int idx) {
    unsigned int kh = ~ford(conf);                        // ascending kh == descending conf
    return ((unsigned long long)kh << 32)
         | ((unsigned long long)(unsigned int)idx << 8)
         | (unsigned long long)bucket_of(conf);
}

// ----------------------------------------------------------------------------
// K0: zero the per-launch counters/histograms
// ----------------------------------------------------------------------------
__global__ void k_zero() {
    int i = blockIdx.x * blockDim.x + threadIdx.x;
    if (i < 2 * (TMAX + 1)) ((int*)g_c)[i] = 0;
    if (i < 2) g_T[i] = 0;
    if (i < 2 * NBKT) { ((int*)g_bcount)[i] = 0; ((int*)g_bfill)[i] = 0; }
}

// ----------------------------------------------------------------------------
// K1: greedy matching per batch. Replicates:
//   for each gt g (in order): claim lowest-index unused proposal with iou > thr
// pot bitmaps stored transposed [z][g][word-of-n] so each greedy step is a
// 125-word scan + shared atomicMin.
// ----------------------------------------------------------------------------
__global__ void __launch_bounds__(256) k_greedy(const float2* __restrict__ segs,
                                                const float2* __restrict__ gts) {
    const int b = blockIdx.x, tid = threadIdx.x;
    extern __shared__ unsigned int pot[];                 // [2][GG][125]
    __shared__ unsigned int used[2][125];
    __shared__ float2 sg[GG];
    __shared__ int s_min;

    if (tid < GG) sg[tid] = gts[b * GG + tid];
    for (int i = tid; i < 2 * GG * 125; i += 256) pot[i] = 0u;
    if (tid < 125) { used[0][tid] = 0u; used[1][tid] = 0u; }
    __syncthreads();

    // candidate bitmaps
    for (int n = tid; n < NN; n += 256) {
        float2 s = segs[b * NN + n];
        float la = s.y - s.x;
        unsigned int wbit = 1u << (n & 31);
        int w = n >> 5;
#pragma unroll 5
        for (int g = 0; g < GG; ++g) {
            float2 t = sg[g];
            float inter = fminf(s.y, t.y) - fmaxf(s.x, t.x);
            inter = fmaxf(inter, 0.0f);
            float uni = la + (t.y - t.x) - inter;
            float iou = inter / uni;
            if (iou > 0.5f)  atomicOr(&pot[(0 * GG + g) * 125 + w], wbit);
            if (iou > 0.75f) atomicOr(&pot[(1 * GG + g) * 125 + w], wbit);
        }
    }
    __syncthreads();

    // greedy claims
    for (int z = 0; z < 2; ++z) {
        for (int g = 0; g < GG; ++g) {
            if (tid == 0) s_min = NN;
            __syncthreads();
            if (tid < 125) {
                unsigned int cand = pot[(z * GG + g) * 125 + tid] & ~used[z][tid];
                if (cand) atomicMin(&s_min, tid * 32 + __ffs((int)cand) - 1);
            }
            __syncthreads();
            if (tid == 0 && s_min < NN) used[z][s_min >> 5] |= 1u << (s_min & 31);
            __syncthreads();
        }
    }

    for (int n = tid; n < NN; n += 256) {
        unsigned int b0 = (used[0][n >> 5] >> (n & 31)) & 1u;
        unsigned int b1 = (used[1][n >> 5] >> (n & 31)) & 1u;
        g_tp[b * NN + n] = (unsigned char)(b0 | (b1 << 1));
    }
}

// ----------------------------------------------------------------------------
// K2: compact TP keys + bucket counts
// ----------------------------------------------------------------------------
__global__ void k_compact(const float* __restrict__ scores) {
    int idx = blockIdx.x * blockDim.x + threadIdx.x;
    if (idx >= M_TOT) return;
    unsigned char tpb = g_tp[idx];
    if (!tpb) return;
    float conf = scores[idx];
    unsigned long long key = make_key(conf, idx);
    int bk = (int)(key & 0xFFull);
    if (tpb & 1) { int p = atomicAdd(&g_T[0], 1); g_list[0][p] = key; atomicAdd(&g_bcount[0][bk], 1); }
    if (tpb & 2) { int p = atomicAdd(&g_T[1], 1); g_list[1][p] = key; atomicAdd(&g_bcount[1][bk], 1); }
}

// K3a: scan bucket counts (tiny)
__global__ void k_bscan() {
    int z = threadIdx.x;
    if (z < 2) {
        int acc = 0;
        for (int i = 0; i < NBKT; ++i) { g_boff[z][i] = acc; acc += g_bcount[z][i]; }
        g_boff[z][NBKT] = acc;
    }
}

// K3b: scatter keys into their buckets
__global__ void k_scatter() {
    int z = blockIdx.y;
    int i = blockIdx.x * blockDim.x + threadIdx.x;
    if (i >= g_T[z]) return;
    unsigned long long key = g_list[z][i];
    int bk = (int)(key & 0xFFull);
    int slot = atomicAdd(&g_bfill[z][bk], 1);
    g_btmp[z][g_boff[z][bk] + slot] = key;
}

// K3c: rank-sort within each bucket (k ~ 50 => O(k^2) trivial)
__global__ void k_bsort() {
    int z = blockIdx.y, bk = blockIdx.x;
    int st = g_boff[z][bk], en = g_boff[z][bk + 1];
    int cnt = en - st;
    for (int i = threadIdx.x; i < cnt; i += blockDim.x) {
        unsigned long long k = g_btmp[z][st + i];
        int r = 0;
        for (int j = 0; j < cnt; ++j) r += (g_btmp[z][st + j] < k) ? 1 : 0;
        g_sorted[z][st + r] = k;
    }
}

// ----------------------------------------------------------------------------
// K4: each of the 1M elements binary-searches its lower-bound position in the
// sorted TP key array (cached in SMEM), histogramming into g_c.
// rank of TP q (elements strictly ahead of it) = prefix(c)[q] - 1.
// ----------------------------------------------------------------------------
__global__ void __launch_bounds__(1024) k_hist(const float* __restrict__ scores) {
    int z = blockIdx.y;
    extern __shared__ unsigned long long sk[];
    int T = g_T[z];
    for (int i = threadIdx.x; i < T; i += 1024) sk[i] = g_sorted[z][i];
    __syncthreads();
    int stride = gridDim.x * 1024;
    for (int idx = blockIdx.x * 1024 + threadIdx.x; idx < M_TOT; idx += stride) {
        unsigned long long key = make_key(scores[idx], idx);
        int lo = 0, hi = T;
        while (lo < hi) {
            int mid = (lo + hi) >> 1;
            if (sk[mid] < key) lo = mid + 1; else hi = mid;
        }
        atomicAdd(&g_c[z][lo], 1);
    }
}

// ----------------------------------------------------------------------------
// K5: finalize AP per threshold.
//   C[q]     = inclusive prefix of c  -> rank_q + 1
//   prec_q   = (q+1)/C[q]
//   suffmax  over q; sum; subtract rank-0 TP's term iff C[0]==1
// ----------------------------------------------------------------------------
__global__ void __launch_bounds__(1024) k_final(float* __restrict__ out) {
    int z = blockIdx.x, tid = threadIdx.x;
    extern __shared__ float smf[];
    float*  prec = smf;                                   // TMAX floats
    int*    auxi = (int*)(smf + TMAX);                    // 1024
    float*  auxf = (float*)(auxi + 1024);                 // 1024
    double* auxd = (double*)(auxf + 1024);                // 1024 (8B aligned: offset 59392)

    int T = g_T[z];
    if (T == 0) { if (tid == 0) out[z] = 0.0f; return; }
    int bins = T + 1;

    // inclusive prefix sum of g_c over [0, bins)
    int CH = (bins + 1023) >> 10;
    int st = min(tid * CH, bins), en = min(st + CH, bins);
    int ssum = 0;
    for (int p = st; p < en; ++p) ssum += g_c[z][p];
    auxi[tid] = ssum;
    __syncthreads();
    if (tid == 0) {
        int acc = 0;
        for (int i = 0; i < 1024; ++i) { int v = auxi[i]; auxi[i] = acc; acc += v; }
    }
    __syncthreads();
    int C = auxi[tid];
    for (int p = st; p < en; ++p) {
        C += g_c[z][p];
        if (p < T) prec[p] = (float)(p + 1) / (float)C;
    }
    __syncthreads();

    // suffix max over [0, T) + weighted sum
    int CH2 = (T + 1023) >> 10;
    int st2 = min(tid * CH2, T), en2 = min(st2 + CH2, T);
    float mx = 0.0f;
    for (int i = st2; i < en2; ++i) mx = fmaxf(mx, prec[i]);
    auxf[tid] = mx;
    __syncthreads();
    if (tid == 0) {
        float acc = 0.0f;
        for (int i = 1023; i >= 0; --i) { float v = auxf[i]; auxf[i] = acc; acc = fmaxf(acc, v); }
    }
    __syncthreads();
    float run = auxf[tid];
    double s = 0.0;
    float m0 = 0.0f;
    for (int i = en2 - 1; i >= st2; --i) {
        run = fmaxf(run, prec[i]);
        s += (double)run;
        if (i == 0) m0 = run;   // global max precision (only reached by tid 0)
    }
    auxd[tid] = s;
    __syncthreads();
    for (int off = 512; off; off >>= 1) {
        if (tid < off) auxd[tid] += auxd[tid + off];
        __syncthreads();
    }
    if (tid == 0) {
        double tot = auxd[0];
        if (g_c[z][0] == 1) tot -= (double)m0;  // TP at global sorted position 0 is excluded
        out[z] = (float)(tot / (double)(BB * GG));
    }
}

// ----------------------------------------------------------------------------
// Launcher (graph-capturable: kernels only, default stream)
// ----------------------------------------------------------------------------
extern "C" void kernel_launch(void* const* d_in, const int* in_sizes, int n_in,
                              void* d_out, int out_size) {
    const float*  scores = (const float*)d_in[0];
    const float2* segs   = (const float2*)d_in[1];
    const float2* gts    = (const float2*)d_in[2];
    float* out = (float*)d_out;

    cudaFuncSetAttribute(k_greedy, cudaFuncAttributeMaxDynamicSharedMemorySize, 2 * GG * 125 * 4);
    cudaFuncSetAttribute(k_hist,   cudaFuncAttributeMaxDynamicSharedMemorySize, TMAX * 8);
    cudaFuncSetAttribute(k_final,  cudaFuncAttributeMaxDynamicSharedMemorySize,
                         TMAX * 4 + 1024 * 4 + 1024 * 4 + 1024 * 8);

    k_zero<<<(2 * (TMAX + 1) + 1023) / 1024, 1024>>>();
    k_greedy<<<BB, 256, 2 * GG * 125 * 4>>>(segs, gts);
    k_compact<<<(M_TOT + 255) / 256, 256>>>(scores);
    k_bscan<<<1, 32>>>();
    k_scatter<<<dim3((TMAX + 255) / 256, 2), 256>>>();
    k_bsort<<<dim3(NBKT, 2), 128>>>();
    k_hist<<<dim3(148, 2), 1024, TMAX * 8>>>(scores);
    k_final<<<2, 1024, TMAX * 4 + 1024 * 4 + 1024 * 4 + 1024 * 8>>>(out);
}

// round 6
// speedup vs baseline: 2.1203x; 2.1203x over previous
#include <cuda_runtime.h>
#include <cuda_bf16.h>

// Problem constants (fixed by the reference setup).
#define BB   256
#define NN   4000
#define GG   50
#define M_TOT (BB * NN)      // 1,024,000 elements
#define TMAX  (BB * GG)      // 12,800 max TPs per threshold
#define NBKT  256
#define NW    125            // 32-bit words covering NN proposals

// ----------------------------------------------------------------------------
// Device scratch (static globals — no allocation allowed)
// ----------------------------------------------------------------------------
__device__ unsigned long long g_list[2][TMAX];       // compacted TP keys (unordered)
__device__ unsigned long long g_sorted[2][TMAX];     // fully sorted ascending keys
__device__ int g_T[2];                               // TP counts
__device__ int g_boff[2][NBKT + 1];                  // bucket offsets (for hist narrowing)
__device__ int g_c[2][TMAX + 1];                     // lower-bound histogram

// ----------------------------------------------------------------------------
// Key construction: ascending key == (conf descending, index ascending).
// Low byte carries the value-based bucket (monotone non-decreasing with key).
// ----------------------------------------------------------------------------
__device__ __forceinline__ unsigned int ford(float f) {
    unsigned int u = __float_as_uint(f);
    return (u & 0x80000000u) ? ~u : (u | 0x80000000u);   // ascending float order
}
__device__ __forceinline__ int bucket_of(float conf) {
    int bi = (int)(conf * 256.0f);
    bi = bi < 0 ? 0 : (bi > 255 ? 255 : bi);
    return 255 - bi;                                      // higher conf -> smaller bucket
}
__device__ __forceinline__ unsigned long long make_key(float conf, int idx) {
    unsigned int kh = ~ford(conf);                        // ascending kh == descending conf
    return ((unsigned long long)kh << 32)
         | ((unsigned long long)(unsigned int)idx << 8)
         | (unsigned long long)bucket_of(conf);
}

// ----------------------------------------------------------------------------
// K0: zero the TP counters (histogram is zeroed inside k_sort)
// ----------------------------------------------------------------------------
__global__ void k_init() {
    if (threadIdx.x < 2) g_T[threadIdx.x] = 0;
}

// ----------------------------------------------------------------------------
// K1: greedy matching per batch + direct TP-key emission.
//   bitmap build: 512 threads, div-free IoU test (inter > thr*uni)
//   claims: warp 0 -> thr 0.5, warp 1 -> thr 0.75, used-mask in REGISTERS,
//           per-gt min via one __reduce_min_sync (no block barriers)
//   emission: scan used words, append keys to g_list via global atomicAdd
// ----------------------------------------------------------------------------
__global__ void __launch_bounds__(512) k_greedy(const float2* __restrict__ segs,
                                                const float2* __restrict__ gts,
                                                const float*  __restrict__ scores) {
    const int b = blockIdx.x, tid = threadIdx.x;
    const int lane = tid & 31, warp = tid >> 5;
    extern __shared__ unsigned int pot[];                 // [2][GG][NW]
    __shared__ unsigned int suse[2][NW];
    __shared__ float2 sg[GG];
    __shared__ float  sglen[GG];

    if (tid < GG) { float2 t = gts[b * GG + tid]; sg[tid] = t; sglen[tid] = t.y - t.x; }
    for (int i = tid; i < 2 * GG * NW; i += 512) pot[i] = 0u;
    __syncthreads();

    // ---- candidate bitmaps ----
    for (int n = tid; n < NN; n += 512) {
        float2 s = segs[b * NN + n];
        float la = s.y - s.x;
        unsigned int wbit = 1u << (n & 31);
        int w = n >> 5;
#pragma unroll 5
        for (int g = 0; g < GG; ++g) {
            float2 t = sg[g];
            float inter = fmaxf(fminf(s.y, t.y) - fmaxf(s.x, t.x), 0.0f);
            float uni = la + sglen[g] - inter;
            // iou > thr  <=>  inter > thr * uni   (uni > 0 always)
            if (inter > 0.5f * uni)  atomicOr(&pot[(0 * GG + g) * NW + w], wbit);
            if (inter > 0.75f * uni) atomicOr(&pot[(1 * GG + g) * NW + w], wbit);
        }
    }
    __syncthreads();

    // ---- greedy claims: one warp per threshold, used bits in registers ----
    if (warp < 2) {
        const int z = warp;
        unsigned int usedreg[4] = {0u, 0u, 0u, 0u};
        const unsigned int* P = pot + z * GG * NW;
        for (int g = 0; g < GG; ++g) {
            unsigned int best = 0xFFFFFFFFu;
#pragma unroll
            for (int s = 0; s < 4; ++s) {
                int w = s * 32 + lane;
                if (w < NW) {
                    unsigned int c = P[g * NW + w] & ~usedreg[s];
                    if (c) {
                        unsigned int cand = (unsigned int)(w * 32 + __ffs(c) - 1);
                        best = min(best, cand);
                    }
                }
            }
            unsigned int m = __reduce_min_sync(0xFFFFFFFFu, best);
            if (m != 0xFFFFFFFFu) {
                int wm = (int)(m >> 5);
                if ((wm & 31) == lane) usedreg[wm >> 5] |= 1u << (m & 31);
            }
        }
#pragma unroll
        for (int s = 0; s < 4; ++s) {
            int w = s * 32 + lane;
            if (w < NW) suse[z][w] = usedreg[s];
        }
    }
    __syncthreads();

    // ---- emit TP keys directly ----
    if (tid < 2 * NW) {
        int z = tid / NW, w = tid % NW;
        unsigned int word = suse[z][w];
        while (word) {
            int bit = __ffs(word) - 1;
            word &= word - 1;
            int idx = b * NN + w * 32 + bit;
            unsigned long long key = make_key(scores[idx], idx);
            int p = atomicAdd(&g_T[z], 1);
            g_list[z][p] = key;
        }
    }
}

// ----------------------------------------------------------------------------
// K2 (fused sort): one block per threshold. SMEM bucket count -> warp-shuffle
// scan -> SMEM scatter -> per-warp rank sort (bucket size ~50). Also writes
// bucket offsets for the hist kernel and zeroes the histogram bins.
// ----------------------------------------------------------------------------
__global__ void __launch_bounds__(1024) k_sort() {
    const int z = blockIdx.x, tid = threadIdx.x;
    const int lane = tid & 31, warp = tid >> 5;
    __shared__ int cnt[NBKT], fill[NBKT], off[NBKT + 1];
    extern __shared__ unsigned long long skeys[];        // TMAX

    int T = g_T[z];
    if (tid < NBKT) { cnt[tid] = 0; fill[tid] = 0; }
    __syncthreads();

    for (int i = tid; i < T; i += 1024)
        atomicAdd(&cnt[(int)(g_list[z][i] & 0xFFull)], 1);
    __syncthreads();

    if (warp == 0) {                                      // exclusive scan of 256 bins
        int base = lane * 8;
        int loc[8]; int s = 0;
#pragma unroll
        for (int j = 0; j < 8; ++j) { loc[j] = s; s += cnt[base + j]; }
        int v = s;
#pragma unroll
        for (int d = 1; d < 32; d <<= 1) {
            int o = __shfl_up_sync(0xFFFFFFFFu, v, d);
            if (lane >= d) v += o;
        }
        int excl = v - s;
#pragma unroll
        for (int j = 0; j < 8; ++j) off[base + j] = excl + loc[j];
        if (lane == 31) off[NBKT] = v;
    }
    __syncthreads();

    for (int i = tid; i < T; i += 1024) {
        unsigned long long k = g_list[z][i];
        int bk = (int)(k & 0xFFull);
        skeys[off[bk] + atomicAdd(&fill[bk], 1)] = k;
    }
    __syncthreads();

    for (int bk = warp; bk < NBKT; bk += 32) {            // rank sort each bucket
        int st = off[bk], en = off[bk + 1];
        for (int i = st + lane; i < en; i += 32) {
            unsigned long long k = skeys[i];
            int r = 0;
            for (int j = st; j < en; ++j) r += (skeys[j] < k) ? 1 : 0;
            g_sorted[z][st + r] = k;
        }
    }

    if (tid <= NBKT) g_boff[z][tid] = off[tid];
    for (int i = tid; i <= T; i += 1024) g_c[z][i] = 0;   // zero hist bins
}

// ----------------------------------------------------------------------------
// K3: lower-bound histogram. Each of the 1M elements searches ONLY its own
// bucket's slice (~50 entries, ~6 dependent LDS steps) of the SMEM-cached
// sorted TP array. Bucket byte is monotone with the key, so the in-bucket
// lower bound equals the global lower bound.
// ----------------------------------------------------------------------------
__global__ void __launch_bounds__(1024) k_hist(const float* __restrict__ scores) {
    const int z = blockIdx.y;
    __shared__ int soff[NBKT + 1];
    extern __shared__ unsigned long long sk[];            // TMAX
    int T = g_T[z];
    for (int i = threadIdx.x; i < T; i += 1024) sk[i] = g_sorted[z][i];
    if (threadIdx.x <= NBKT) soff[threadIdx.x] = g_boff[z][threadIdx.x];
    __syncthreads();

    int stride = gridDim.x * 1024;
    for (int idx = blockIdx.x * 1024 + threadIdx.x; idx < M_TOT; idx += stride) {
        unsigned long long key = make_key(__ldg(&scores[idx]), idx);
        int bk = (int)(key & 0xFFull);
        int lo = soff[bk], hi = soff[bk + 1];
        while (lo < hi) {
            int mid = (lo + hi) >> 1;
            if (sk[mid] < key) lo = mid + 1; else hi = mid;
        }
        atomicAdd(&g_c[z][lo], 1);
    }
}

// ----------------------------------------------------------------------------
// K4: finalize AP per threshold — all scans parallel (warp shuffles):
//   C[q] = inclusive prefix of c  -> rank_q + 1
//   prec_q = (q+1)/C[q];  suffix-max;  sum;  subtract global-max iff c[0]==1
// ----------------------------------------------------------------------------
__global__ void __launch_bounds__(1024) k_final(float* __restrict__ out) {
    const int z = blockIdx.x, tid = threadIdx.x;
    const int lane = tid & 31, warp = tid >> 5;
    __shared__ int    wsum[32];
    __shared__ float  wmax[32];
    __shared__ double wdbl[32];
    __shared__ float  s_suf[1024];
    __shared__ float  s_gmax;
    extern __shared__ float prec[];                       // TMAX

    int T = g_T[z];
    if (T == 0) { if (tid == 0) out[z] = 0.0f; return; }
    int bins = T + 1;
    int CH = (bins + 1023) >> 10;
    int st = min(tid * CH, bins), en = min(st + CH, bins);

    // ---- block-wide exclusive prefix sum of per-thread bin sums ----
    int ssum = 0;
    for (int p = st; p < en; ++p) ssum += g_c[z][p];
    int v = ssum;
#pragma unroll
    for (int d = 1; d < 32; d <<= 1) {
        int o = __shfl_up_sync(0xFFFFFFFFu, v, d);
        if (lane >= d) v += o;
    }
    if (lane == 31) wsum[warp] = v;
    __syncthreads();
    if (warp == 0) {
        int w = wsum[lane], wi = w;
#pragma unroll
        for (int d = 1; d < 32; d <<= 1) {
            int o = __shfl_up_sync(0xFFFFFFFFu, wi, d);
            if (lane >= d) wi += o;
        }
        wsum[lane] = wi - w;                              // exclusive warp offsets
    }
    __syncthreads();
    int C = wsum[warp] + (v - ssum);                      // exclusive prefix for this thread

    // ---- precision values + chunk max ----
    float mx = 0.0f;
    for (int p = st; p < en; ++p) {
        C += g_c[z][p];
        if (p < T) {
            float pr = (float)(p + 1) / (float)C;
            prec[p] = pr;
            mx = fmaxf(mx, pr);
        }
    }

    // ---- exclusive suffix-max over chunks (reversed exclusive max-scan) ----
    s_suf[1023 - tid] = mx;
    __syncthreads();
    float a = s_suf[tid], ai = a;
#pragma unroll
    for (int d = 1; d < 32; d <<= 1) {
        float o = __shfl_up_sync(0xFFFFFFFFu, ai, d);
        if (lane >= d) ai = fmaxf(ai, o);
    }
    float le = __shfl_up_sync(0xFFFFFFFFu, ai, 1);        // lane-exclusive within warp
    if (lane == 0) le = 0.0f;
    if (lane == 31) wmax[warp] = ai;
    __syncthreads();
    if (warp == 0) {
        float w0 = wmax[lane], wi = w0;
#pragma unroll
        for (int d = 1; d < 32; d <<= 1) {
            float o = __shfl_up_sync(0xFFFFFFFFu, wi, d);
            if (lane >= d) wi = fmaxf(wi, o);
        }
        float e = __shfl_up_sync(0xFFFFFFFFu, wi, 1);
        if (lane == 0) e = 0.0f;
        wmax[lane] = e;                                   // exclusive warp max offsets
        if (lane == 31) s_gmax = wi;                      // global max precision
    }
    __syncthreads();
    float suf_excl = fmaxf(wmax[warp], le);               // excl max for reversed pos tid
    s_suf[tid] = suf_excl;
    __syncthreads();
    float run = s_suf[1023 - tid];                        // max over chunks after this one
    __syncthreads();

    // ---- weighted sum (descending within chunk, running suffix max) ----
    double s = 0.0;
    int hi = min(en, T);
    for (int p = hi - 1; p >= st; --p) {
        run = fmaxf(run, prec[p]);
        s += (double)run;
    }

    // ---- double reduction ----
#pragma unroll
    for (int d = 16; d; d >>= 1) s += __shfl_down_sync(0xFFFFFFFFu, s, d);
    if (lane == 0) wdbl[warp] = s;
    __syncthreads();
    if (warp == 0) {
        double t = wdbl[lane];
#pragma unroll
        for (int d = 16; d; d >>= 1) t += __shfl_down_sync(0xFFFFFFFFu, t, d);
        if (lane == 0) {
            if (g_c[z][0] == 1) t -= (double)s_gmax;      // rank-0 TP excluded
            out[z] = (float)(t / (double)(BB * GG));
        }
    }
}

// ----------------------------------------------------------------------------
// Launcher (graph-capturable: kernels only, default stream)
// ----------------------------------------------------------------------------
extern "C" void kernel_launch(void* const* d_in, const int* in_sizes, int n_in,
                              void* d_out, int out_size) {
    const float*  scores = (const float*)d_in[0];
    const float2* segs   = (const float2*)d_in[1];
    const float2* gts    = (const float2*)d_in[2];
    float* out = (float*)d_out;

    cudaFuncSetAttribute(k_greedy, cudaFuncAttributeMaxDynamicSharedMemorySize, 2 * GG * NW * 4);
    cudaFuncSetAttribute(k_sort,   cudaFuncAttributeMaxDynamicSharedMemorySize, TMAX * 8);
    cudaFuncSetAttribute(k_hist,   cudaFuncAttributeMaxDynamicSharedMemorySize, TMAX * 8);
    cudaFuncSetAttribute(k_final,  cudaFuncAttributeMaxDynamicSharedMemorySize, TMAX * 4);

    k_init<<<1, 32>>>();
    k_greedy<<<BB, 512, 2 * GG * NW * 4>>>(segs, gts, scores);
    k_sort<<<2, 1024, TMAX * 8>>>();
    k_hist<<<dim3(148, 2), 1024, TMAX * 8>>>(scores);
    k_final<<<2, 1024, TMAX * 4>>>(out);
}

// round 7
// speedup vs baseline: 2.1482x; 1.0131x over previous
#include <cuda_runtime.h>
#include <cuda_bf16.h>

// Problem constants (fixed by the reference setup).
#define BB   256
#define NN   4000
#define GG   50
#define M_TOT (BB * NN)      // 1,024,000 elements
#define TMAX  (BB * GG)      // 12,800 max TPs per threshold
#define NBKT  4096           // 12-bit value buckets
#define NW    125            // 32-bit words covering NN proposals (125*32 == 4000)

// ----------------------------------------------------------------------------
// Device scratch (static globals — no allocation allowed)
// ----------------------------------------------------------------------------
__device__ unsigned long long g_list[2][TMAX];       // compacted TP keys (unordered)
__device__ unsigned long long g_sorted[2][TMAX];     // fully sorted ascending keys
__device__ int g_T[2];                               // TP counts (zero at load; restored by k_final)
__device__ int g_boff[2][NBKT + 1];                  // bucket offsets (for hist narrowing)
__device__ int g_c[2][TMAX + 1];                     // lower-bound histogram

// ----------------------------------------------------------------------------
// Key: ascending key == (conf descending, index ascending).
// Layout: [conf-ord 32][idx 20][bucket 12]; bucket is monotone with the key.
// ----------------------------------------------------------------------------
__device__ __forceinline__ unsigned int ford(float f) {
    unsigned int u = __float_as_uint(f);
    return (u & 0x80000000u) ? ~u : (u | 0x80000000u);   // ascending float order
}
__device__ __forceinline__ int bucket_of(float conf) {
    int bi = (int)(conf * 4096.0f);
    bi = bi < 0 ? 0 : (bi > 4095 ? 4095 : bi);
    return 4095 - bi;                                     // higher conf -> smaller bucket
}
__device__ __forceinline__ unsigned long long make_key(float conf, int idx) {
    unsigned int kh = ~ford(conf);                        // ascending kh == descending conf
    return ((unsigned long long)kh << 32)
         | ((unsigned long long)(unsigned int)idx << 12)
         | (unsigned long long)bucket_of(conf);
}

// ----------------------------------------------------------------------------
// K1: greedy matching per batch + direct TP-key emission.
//   bitmaps: each warp owns 32 consecutive proposals -> one word per (warp,g);
//            built with __ballot_sync + single STS. No atomics, no zero-init.
//   claims:  warp z handles threshold z; used-mask in registers; one
//            __reduce_min_sync per gt. No block barriers in the loop.
// ----------------------------------------------------------------------------
__global__ void __launch_bounds__(512) k_greedy(const float2* __restrict__ segs,
                                                const float2* __restrict__ gts,
                                                const float*  __restrict__ scores) {
    const int b = blockIdx.x, tid = threadIdx.x;
    const int lane = tid & 31, warp = tid >> 5;           // 16 warps
    extern __shared__ unsigned int pot[];                 // [2][GG][NW]
    __shared__ unsigned int suse[2][NW];
    __shared__ float4 sg[GG];                             // {tx, ty, len, pad}

    if (tid < GG) {
        float2 t = gts[b * GG + tid];
        sg[tid] = make_float4(t.x, t.y, t.y - t.x, 0.0f);
    }
    __syncthreads();

    // ---- candidate bitmaps: warp covers word w (lanes = consecutive n) ----
    for (int w = warp; w < NW; w += 16) {
        int n = w * 32 + lane;                            // always < 4000
        float2 s = segs[b * NN + n];
        float la = s.y - s.x;
#pragma unroll 10
        for (int g = 0; g < GG; ++g) {
            float4 t = sg[g];                             // broadcast LDS.128
            float inter = fminf(s.y, t.y) - fmaxf(s.x, t.x);
            float ssum  = la + t.z;                       // la + lg  (> 0)
            // iou > 0.5  <=> 3*inter > la+lg ; iou > 0.75 <=> 7*inter > 3*(la+lg)
            unsigned int b0 = __ballot_sync(0xFFFFFFFFu, 3.0f * inter > ssum);
            unsigned int b1 = __ballot_sync(0xFFFFFFFFu, 7.0f * inter > 3.0f * ssum);
            if (lane == 0) {
                pot[g * NW + w]        = b0;
                pot[(GG + g) * NW + w] = b1;
            }
        }
    }
    __syncthreads();

    // ---- greedy claims: one warp per threshold, used bits in registers ----
    if (warp < 2) {
        const int z = warp;
        unsigned int usedreg[4] = {0u, 0u, 0u, 0u};
        const unsigned int* P = pot + z * GG * NW;
        for (int g = 0; g < GG; ++g) {
            unsigned int best = 0xFFFFFFFFu;
#pragma unroll
            for (int s = 0; s < 4; ++s) {
                int w = s * 32 + lane;
                if (w < NW) {
                    unsigned int c = P[g * NW + w] & ~usedreg[s];
                    if (c) best = min(best, (unsigned int)(w * 32 + __ffs(c) - 1));
                }
            }
            unsigned int m = __reduce_min_sync(0xFFFFFFFFu, best);
            if (m != 0xFFFFFFFFu) {
                int wm = (int)(m >> 5);
                if ((wm & 31) == lane) usedreg[wm >> 5] |= 1u << (m & 31);
            }
        }
#pragma unroll
        for (int s = 0; s < 4; ++s) {
            int w = s * 32 + lane;
            if (w < NW) suse[z][w] = usedreg[s];
        }
    }
    __syncthreads();

    // ---- emit TP keys directly ----
    if (tid < 2 * NW) {
        int z = tid / NW, w = tid % NW;
        unsigned int word = suse[z][w];
        while (word) {
            int bit = __ffs(word) - 1;
            word &= word - 1;
            int idx = b * NN + w * 32 + bit;
            unsigned long long key = make_key(scores[idx], idx);
            int p = atomicAdd(&g_T[z], 1);
            g_list[z][p] = key;
        }
    }
}

// ----------------------------------------------------------------------------
// K2 (fused sort): one block per threshold. 4096-bin count -> block scan ->
// scatter -> thread-per-bucket insertion (avg 3 keys/bucket). Writes bucket
// offsets for k_hist and zeroes the histogram bins.
// ----------------------------------------------------------------------------
__global__ void __launch_bounds__(1024) k_sort() {
    const int z = blockIdx.x, tid = threadIdx.x;
    const int lane = tid & 31, warp = tid >> 5;
    extern __shared__ int ssort[];
    int* cnt  = ssort;                                    // 4096
    int* fill = ssort + NBKT;                             // 4096
    int* off  = ssort + 2 * NBKT;                         // 4097
    unsigned long long* skeys = (unsigned long long*)(ssort + 2 * NBKT + 4098); // 8B aligned
    __shared__ int wtot[32];

    int T = g_T[z];
#pragma unroll
    for (int j = 0; j < 4; ++j) { cnt[tid * 4 + j] = 0; fill[tid * 4 + j] = 0; }
    __syncthreads();

    for (int i = tid; i < T; i += 1024)
        atomicAdd(&cnt[(int)(g_list[z][i] & 0xFFFull)], 1);
    __syncthreads();

    // block-wide exclusive scan: each thread owns 4 consecutive bins
    int base = tid * 4;
    int loc[4]; int s = 0;
#pragma unroll
    for (int j = 0; j < 4; ++j) { loc[j] = s; s += cnt[base + j]; }
    int v = s;
#pragma unroll
    for (int d = 1; d < 32; d <<= 1) {
        int o = __shfl_up_sync(0xFFFFFFFFu, v, d);
        if (lane >= d) v += o;
    }
    if (lane == 31) wtot[warp] = v;
    __syncthreads();
    if (warp == 0) {
        int w = wtot[lane], wi = w;
#pragma unroll
        for (int d = 1; d < 32; d <<= 1) {
            int o = __shfl_up_sync(0xFFFFFFFFu, wi, d);
            if (lane >= d) wi += o;
        }
        wtot[lane] = wi - w;
    }
    __syncthreads();
    int excl = wtot[warp] + (v - s);
#pragma unroll
    for (int j = 0; j < 4; ++j) off[base + j] = excl + loc[j];
    if (tid == 1023) off[NBKT] = excl + s;
    __syncthreads();

    for (int i = tid; i < T; i += 1024) {
        unsigned long long k = g_list[z][i];
        int bk = (int)(k & 0xFFFull);
        skeys[off[bk] + atomicAdd(&fill[bk], 1)] = k;
    }
    __syncthreads();

    // thread-per-bucket rank sort (buckets are tiny)
    for (int bk = tid; bk < NBKT; bk += 1024) {
        int st = off[bk], en = off[bk + 1];
        for (int i = st; i < en; ++i) {
            unsigned long long k = skeys[i];
            int r = 0;
            for (int j = st; j < en; ++j) r += (skeys[j] < k) ? 1 : 0;
            g_sorted[z][st + r] = k;
        }
    }

    for (int i = tid; i <= NBKT; i += 1024) g_boff[z][i] = off[i];
    for (int i = tid; i <= T; i += 1024) g_c[z][i] = 0;   // zero hist bins
}

// ----------------------------------------------------------------------------
// K3: lower-bound histogram. 4096-way bucket narrows the search to ~3 keys
// (~2 dependent LDS levels). Bucket byte monotone with key => in-bucket lower
// bound == global lower bound.
// ----------------------------------------------------------------------------
__global__ void __launch_bounds__(1024) k_hist(const float* __restrict__ scores) {
    const int z = blockIdx.y;
    extern __shared__ int sh[];
    int* soff = sh;                                       // 4097
    unsigned long long* sk = (unsigned long long*)(sh + 4098); // 8B aligned
    int T = g_T[z];
    for (int i = threadIdx.x; i < T; i += 1024) sk[i] = g_sorted[z][i];
    for (int i = threadIdx.x; i <= NBKT; i += 1024) soff[i] = g_boff[z][i];
    __syncthreads();

    int stride = gridDim.x * 1024;
    for (int idx = blockIdx.x * 1024 + threadIdx.x; idx < M_TOT; idx += stride) {
        unsigned long long key = make_key(__ldg(&scores[idx]), idx);
        int bk = (int)(key & 0xFFFull);
        int lo = soff[bk], hi = soff[bk + 1];
        while (lo < hi) {
            int mid = (lo + hi) >> 1;
            if (sk[mid] < key) lo = mid + 1; else hi = mid;
        }
        atomicAdd(&g_c[z][lo], 1);
    }
}

// ----------------------------------------------------------------------------
// K4: finalize AP per threshold — all scans parallel (warp shuffles). Resets
// g_T at the tail so the next graph replay starts from the load-time state.
// ----------------------------------------------------------------------------
__global__ void __launch_bounds__(1024) k_final(float* __restrict__ out) {
    const int z = blockIdx.x, tid = threadIdx.x;
    const int lane = tid & 31, warp = tid >> 5;
    __shared__ int    wsum[32];
    __shared__ float  wmax[32];
    __shared__ double wdbl[32];
    __shared__ float  s_suf[1024];
    __shared__ float  s_gmax;
    extern __shared__ float prec[];                       // TMAX

    int T = g_T[z];
    if (T == 0) { if (tid == 0) { out[z] = 0.0f; g_T[z] = 0; } return; }
    int bins = T + 1;
    int CH = (bins + 1023) >> 10;
    int st = min(tid * CH, bins), en = min(st + CH, bins);

    // ---- block-wide exclusive prefix sum of per-thread bin sums ----
    int ssum = 0;
    for (int p = st; p < en; ++p) ssum += g_c[z][p];
    int v = ssum;
#pragma unroll
    for (int d = 1; d < 32; d <<= 1) {
        int o = __shfl_up_sync(0xFFFFFFFFu, v, d);
        if (lane >= d) v += o;
    }
    if (lane == 31) wsum[warp] = v;
    __syncthreads();
    if (warp == 0) {
        int w = wsum[lane], wi = w;
#pragma unroll
        for (int d = 1; d < 32; d <<= 1) {
            int o = __shfl_up_sync(0xFFFFFFFFu, wi, d);
            if (lane >= d) wi += o;
        }
        wsum[lane] = wi - w;
    }
    __syncthreads();
    int C = wsum[warp] + (v - ssum);

    // ---- precision values + chunk max ----
    float mx = 0.0f;
    for (int p = st; p < en; ++p) {
        C += g_c[z][p];
        if (p < T) {
            float pr = (float)(p + 1) / (float)C;
            prec[p] = pr;
            mx = fmaxf(mx, pr);
        }
    }

    // ---- exclusive suffix-max over chunks (reversed exclusive max-scan) ----
    s_suf[1023 - tid] = mx;
    __syncthreads();
    float a = s_suf[tid], ai = a;
#pragma unroll
    for (int d = 1; d < 32; d <<= 1) {
        float o = __shfl_up_sync(0xFFFFFFFFu, ai, d);
        if (lane >= d) ai = fmaxf(ai, o);
    }
    float le = __shfl_up_sync(0xFFFFFFFFu, ai, 1);
    if (lane == 0) le = 0.0f;
    if (lane == 31) wmax[warp] = ai;
    __syncthreads();
    if (warp == 0) {
        float w0 = wmax[lane], wi = w0;
#pragma unroll
        for (int d = 1; d < 32; d <<= 1) {
            float o = __shfl_up_sync(0xFFFFFFFFu, wi, d);
            if (lane >= d) wi = fmaxf(wi, o);
        }
        float e = __shfl_up_sync(0xFFFFFFFFu, wi, 1);
        if (lane == 0) e = 0.0f;
        wmax[lane] = e;
        if (lane == 31) s_gmax = wi;                      // global max precision
    }
    __syncthreads();
    float suf_excl = fmaxf(wmax[warp], le);
    s_suf[tid] = suf_excl;
    __syncthreads();
    float run = s_suf[1023 - tid];
    __syncthreads();

    // ---- weighted sum (descending within chunk, running suffix max) ----
    double s = 0.0;
    int hi = min(en, T);
    for (int p = hi - 1; p >= st; --p) {
        run = fmaxf(run, prec[p]);
        s += (double)run;
    }

    // ---- double reduction ----
#pragma unroll
    for (int d = 16; d; d >>= 1) s += __shfl_down_sync(0xFFFFFFFFu, s, d);
    if (lane == 0) wdbl[warp] = s;
    __syncthreads();
    if (warp == 0) {
        double t = wdbl[lane];
#pragma unroll
        for (int d = 16; d; d >>= 1) t += __shfl_down_sync(0xFFFFFFFFu, t, d);
        if (lane == 0) {
            if (g_c[z][0] == 1) t -= (double)s_gmax;      // rank-0 TP excluded
            out[z] = (float)(t / (double)(BB * GG));
            g_T[z] = 0;                                   // restore invariant for next replay
        }
    }
}

// ----------------------------------------------------------------------------
// Launcher (graph-capturable: kernels only, default stream)
// ----------------------------------------------------------------------------
extern "C" void kernel_launch(void* const* d_in, const int* in_sizes, int n_in,
                              void* d_out, int out_size) {
    const float*  scores = (const float*)d_in[0];
    const float2* segs   = (const float2*)d_in[1];
    const float2* gts    = (const float2*)d_in[2];
    float* out = (float*)d_out;

    const int smem_greedy = 2 * GG * NW * 4;                       // 50,000 B
    const int smem_sort   = (2 * NBKT + 4098) * 4 + TMAX * 8;      // 151,592 B
    const int smem_hist   = 4098 * 4 + TMAX * 8;                   // 118,792 B
    const int smem_final  = TMAX * 4;                              //  51,200 B

    cudaFuncSetAttribute(k_greedy, cudaFuncAttributeMaxDynamicSharedMemorySize, smem_greedy);
    cudaFuncSetAttribute(k_sort,   cudaFuncAttributeMaxDynamicSharedMemorySize, smem_sort);
    cudaFuncSetAttribute(k_hist,   cudaFuncAttributeMaxDynamicSharedMemorySize, smem_hist);
    cudaFuncSetAttribute(k_final,  cudaFuncAttributeMaxDynamicSharedMemorySize, smem_final);

    k_greedy<<<BB, 512, smem_greedy>>>(segs, gts, scores);
    k_sort<<<2, 1024, smem_sort>>>();
    k_hist<<<dim3(148, 2), 1024, smem_hist>>>(scores);
    k_final<<<2, 1024, smem_final>>>(out);
}

// round 9
// speedup vs baseline: 2.4226x; 1.1278x over previous
#include <cuda_runtime.h>
#include <cuda_bf16.h>

// Problem constants (fixed by the reference setup).
#define BB   256
#define NN   4000
#define GG   50
#define M_TOT (BB * NN)      // 1,024,000 elements
#define TMAX  (BB * GG)      // 12,800 max TPs per threshold
#define NBKT  4096           // 12-bit value buckets
#define NW    125            // 32-bit words covering NN proposals (125*32 == 4000)

// ----------------------------------------------------------------------------
// Device scratch (static globals — zero-initialized at load; every kernel that
// consumes a counter restores it to zero, so graph replays are deterministic)
// ----------------------------------------------------------------------------
__device__ unsigned long long g_list[2][TMAX];       // compacted TP keys (unordered)
__device__ unsigned long long g_sorted[2][TMAX];     // fully sorted ascending keys
__device__ int g_T[2];                               // TP counts
__device__ __align__(16) int g_bcount[2][NBKT];      // bucket counts (filled by greedy)
__device__ int g_boff[2][NBKT + 1];                  // bucket offsets
__device__ int g_c[2][TMAX + 1];                     // lower-bound histogram

// ----------------------------------------------------------------------------
// Key: ascending key == (conf descending, index ascending).
// Layout: [conf-ord 32][idx 20][bucket 12]; bucket is monotone with the key.
// ----------------------------------------------------------------------------
__device__ __forceinline__ unsigned int ford(float f) {
    unsigned int u = __float_as_uint(f);
    return (u & 0x80000000u) ? ~u : (u | 0x80000000u);   // ascending float order
}
__device__ __forceinline__ int bucket_of(float conf) {
    int bi = (int)(conf * 4096.0f);
    bi = bi < 0 ? 0 : (bi > 4095 ? 4095 : bi);
    return 4095 - bi;                                     // higher conf -> smaller bucket
}
__device__ __forceinline__ unsigned long long make_key(float conf, int idx) {
    unsigned int kh = ~ford(conf);                        // ascending kh == descending conf
    return ((unsigned long long)kh << 32)
         | ((unsigned long long)(unsigned int)idx << 12)
         | (unsigned long long)bucket_of(conf);
}

// ----------------------------------------------------------------------------
// K1: greedy matching per batch + direct TP-key emission.
//   gts sorted by start; per proposal only the [s.x - max_len, s.y) window of
//   gts is tested (exact IoU tests inside -> bit-identical bitmaps). Sparse
//   atomicOr only on passing pairs. Claims: warp z per threshold, used-mask
//   in registers, one __reduce_min_sync per gt. Also zeroes g_c and feeds
//   g_bcount so k_sort can skip its counting pass.
// ----------------------------------------------------------------------------
__global__ void __launch_bounds__(512) k_greedy(const float2* __restrict__ segs,
                                                const float2* __restrict__ gts,
                                                const float*  __restrict__ scores) {
    const int b = blockIdx.x, tid = threadIdx.x;
    const int lane = tid & 31, warp = tid >> 5;           // 16 warps
    extern __shared__ unsigned int pot[];                 // [2][GG][NW]
    __shared__ float4 sgt[GG];                            // sorted: {x, y, len, idx-bits}
    __shared__ float2 raw[GG];
    __shared__ unsigned int suse[2][NW];
    __shared__ int s_tab[64];
    __shared__ int s_maxlen;                              // float bits (positive)

    // zero bitmaps + zero this launch's g_c slice (distributed over 256 blocks)
    for (int i = tid; i < 2 * GG * NW; i += 512) pot[i] = 0u;
    for (int i = b * 512 + tid; i < 2 * (TMAX + 1); i += BB * 512) ((int*)g_c)[i] = 0;
    if (tid == 0) s_maxlen = 0;
    if (tid < GG) raw[tid] = gts[b * GG + tid];
    __syncthreads();

    // sort gts by start (rank sort, stable on ties) + max length
    if (tid < GG) {
        float2 t = raw[tid];
        int r = 0;
        for (int j = 0; j < GG; ++j) {
            float xj = raw[j].x;
            r += (xj < t.x) || (xj == t.x && j < tid);
        }
        sgt[r] = make_float4(t.x, t.y, t.y - t.x, __int_as_float(tid));
        atomicMax(&s_maxlen, __float_as_int(t.y - t.x)); // positive floats: int cmp ok
    }
    __syncthreads();
    // 64-entry start table: s_tab[q] = first j with sgt[j].x >= q/64
    if (tid < 64) {
        float thr = (float)tid * (1.0f / 64.0f);
        int j = 0;
        while (j < GG && sgt[j].x < thr) ++j;
        s_tab[tid] = j;
    }
    __syncthreads();
    const float maxlg = __int_as_float(s_maxlen);

    // ---- candidate evaluation over the pruned gt window ----
    for (int n = tid; n < NN; n += 512) {
        float2 s = segs[b * NN + n];
        float la = s.y - s.x;
        float xlo = s.x - maxlg;
        int q = (int)(xlo * 64.0f) - 1;                   // -1: conservative vs fp round-up
        q = q < 0 ? 0 : (q > 63 ? 63 : q);
        int w = n >> 5;
        unsigned int wbit = 1u << (n & 31);
        for (int j = s_tab[q]; j < GG; ++j) {
            float4 t = sgt[j];                            // LDS.128
            if (t.x >= s.y) break;                        // inter <= 0 beyond here
            float inter = fminf(s.y, t.y) - fmaxf(s.x, t.x);
            float ssum  = la + t.z;                       // la + lg (> 0)
            int g = __float_as_int(t.w);
            // iou > 0.5 <=> 3*inter > la+lg ; iou > 0.75 <=> 7*inter > 3*(la+lg)
            if (3.0f * inter > ssum)         atomicOr(&pot[g * NW + w], wbit);
            if (7.0f * inter > 3.0f * ssum)  atomicOr(&pot[(GG + g) * NW + w], wbit);
        }
    }
    __syncthreads();

    // ---- greedy claims: one warp per threshold, used bits in registers ----
    if (warp < 2) {
        const int z = warp;
        unsigned int usedreg[4] = {0u, 0u, 0u, 0u};
        const unsigned int* P = pot + z * GG * NW;
        for (int g = 0; g < GG; ++g) {
            unsigned int best = 0xFFFFFFFFu;
#pragma unroll
            for (int s = 0; s < 4; ++s) {
                int w = s * 32 + lane;
                if (w < NW) {
                    unsigned int c = P[g * NW + w] & ~usedreg[s];
                    if (c) best = min(best, (unsigned int)(w * 32 + __ffs(c) - 1));
                }
            }
            unsigned int m = __reduce_min_sync(0xFFFFFFFFu, best);
            if (m != 0xFFFFFFFFu) {
                int wm = (int)(m >> 5);
                if ((wm & 31) == lane) usedreg[wm >> 5] |= 1u << (m & 31);
            }
        }
#pragma unroll
        for (int s = 0; s < 4; ++s) {
            int w = s * 32 + lane;
            if (w < NW) suse[z][w] = usedreg[s];
        }
    }
    __syncthreads();

    // ---- emit TP keys + bucket counts ----
    if (tid < 2 * NW) {
        int z = tid / NW, w = tid % NW;
        unsigned int word = suse[z][w];
        while (word) {
            int bit = __ffs(word) - 1;
            word &= word - 1;
            int idx = b * NN + w * 32 + bit;
            unsigned long long key = make_key(scores[idx], idx);
            int p = atomicAdd(&g_T[z], 1);
            g_list[z][p] = key;
            atomicAdd(&g_bcount[z][(int)(key & 0xFFFull)], 1);
        }
    }
}

// ----------------------------------------------------------------------------
// K2 (fused sort): one block per threshold. Consumes g_bcount (then rezeroes
// it for the next replay) -> block scan -> single-pass scatter -> thread-per-
// bucket rank sort. Writes g_boff for k_hist.
// SMEM layout (ints): off[0..NBKT] | pad to 16B | fill[NBKT] | skeys (8B-aligned)
// ----------------------------------------------------------------------------
__global__ void __launch_bounds__(1024) k_sort() {
    const int z = blockIdx.x, tid = threadIdx.x;
    const int lane = tid & 31, warp = tid >> 5;
    extern __shared__ int ssort[];
    int* off  = ssort;                                    // NBKT+1 ints
    int* fill = ssort + NBKT + 4;                         // byte 16400 = 16-aligned
    unsigned long long* skeys = (unsigned long long*)(ssort + 2 * NBKT + 4); // byte 32784, 8-aligned
    __shared__ int wtot[32];

    int T = g_T[z];

    // load 4 consecutive bucket counts (g_bcount 16-aligned), restore to zero
    int4* bc = (int4*)&g_bcount[z][0];
    int4 c4 = bc[tid];
    bc[tid] = make_int4(0, 0, 0, 0);
    ((int4*)fill)[tid] = make_int4(0, 0, 0, 0);

    // block-wide exclusive scan over 4096 bins (4 per thread)
    int loc[4]; int s = 0;
    loc[0] = s; s += c4.x; loc[1] = s; s += c4.y;
    loc[2] = s; s += c4.z; loc[3] = s; s += c4.w;
    int v = s;
#pragma unroll
    for (int d = 1; d < 32; d <<= 1) {
        int o = __shfl_up_sync(0xFFFFFFFFu, v, d);
        if (lane >= d) v += o;
    }
    if (lane == 31) wtot[warp] = v;
    __syncthreads();
    if (warp == 0) {
        int w = wtot[lane], wi = w;
#pragma unroll
        for (int d = 1; d < 32; d <<= 1) {
            int o = __shfl_up_sync(0xFFFFFFFFu, wi, d);
            if (lane >= d) wi += o;
        }
        wtot[lane] = wi - w;
    }
    __syncthreads();
    int excl = wtot[warp] + (v - s);
    int base = tid * 4;
#pragma unroll
    for (int j = 0; j < 4; ++j) off[base + j] = excl + loc[j];
    if (tid == 1023) off[NBKT] = excl + s;
    __syncthreads();

    // single global pass: keys -> registers -> smem scatter
    for (int i = tid; i < T; i += 1024) {
        unsigned long long k = g_list[z][i];
        int bk = (int)(k & 0xFFFull);
        skeys[off[bk] + atomicAdd(&fill[bk], 1)] = k;
    }
    __syncthreads();

    // thread-per-bucket rank sort (avg ~3 keys/bucket)
    for (int bk = tid; bk < NBKT; bk += 1024) {
        int st = off[bk], en = off[bk + 1];
        for (int i = st; i < en; ++i) {
            unsigned long long k = skeys[i];
            int r = 0;
            for (int j = st; j < en; ++j) r += (skeys[j] < k) ? 1 : 0;
            g_sorted[z][st + r] = k;
        }
    }

    for (int i = tid; i <= NBKT; i += 1024) g_boff[z][i] = off[i];
}

// ----------------------------------------------------------------------------
// K3: lower-bound histogram. 4096-way bucket narrows the search to ~3 keys
// (~2 dependent LDS levels). In-bucket lower bound == global lower bound.
// ----------------------------------------------------------------------------
__global__ void __launch_bounds__(1024) k_hist(const float* __restrict__ scores) {
    const int z = blockIdx.y;
    extern __shared__ int sh[];
    int* soff = sh;                                       // NBKT+1
    unsigned long long* sk = (unsigned long long*)(sh + NBKT + 2); // byte 16392, 8-aligned
    int T = g_T[z];
    for (int i = threadIdx.x; i < T; i += 1024) sk[i] = g_sorted[z][i];
    for (int i = threadIdx.x; i <= NBKT; i += 1024) soff[i] = g_boff[z][i];
    __syncthreads();

    int stride = gridDim.x * 1024;
    for (int idx = blockIdx.x * 1024 + threadIdx.x; idx < M_TOT; idx += stride) {
        unsigned long long key = make_key(__ldg(&scores[idx]), idx);
        int bk = (int)(key & 0xFFFull);
        int lo = soff[bk], hi = soff[bk + 1];
        while (lo < hi) {
            int mid = (lo + hi) >> 1;
            if (sk[mid] < key) lo = mid + 1; else hi = mid;
        }
        atomicAdd(&g_c[z][lo], 1);
    }
}

// ----------------------------------------------------------------------------
// K4: finalize AP per threshold. g_c staged into SMEM coalesced; the blocked
// per-thread chunk loops then run out of SMEM (stride-13 = conflict-free).
// Resets g_T at the tail for the next graph replay.
// ----------------------------------------------------------------------------
__global__ void __launch_bounds__(1024) k_final(float* __restrict__ out) {
    const int z = blockIdx.x, tid = threadIdx.x;
    const int lane = tid & 31, warp = tid >> 5;
    __shared__ int    wsum[32];
    __shared__ float  wmax[32];
    __shared__ double wdbl[32];
    __shared__ float  s_suf[1024];
    __shared__ float  s_gmax;
    extern __shared__ int sfin[];
    int*   s_c  = sfin;                                   // TMAX+1 (+pad)
    float* prec = (float*)(sfin + TMAX + 4);              // TMAX

    int T = g_T[z];
    if (T == 0) { if (tid == 0) { out[z] = 0.0f; g_T[z] = 0; } return; }
    int bins = T + 1;

    // coalesced stage of the histogram
    for (int i = tid; i < bins; i += 1024) s_c[i] = g_c[z][i];
    __syncthreads();

    int CH = (bins + 1023) >> 10;
    int st = min(tid * CH, bins), en = min(st + CH, bins);

    // ---- block-wide exclusive prefix sum of per-thread bin sums ----
    int ssum = 0;
    for (int p = st; p < en; ++p) ssum += s_c[p];
    int v = ssum;
#pragma unroll
    for (int d = 1; d < 32; d <<= 1) {
        int o = __shfl_up_sync(0xFFFFFFFFu, v, d);
        if (lane >= d) v += o;
    }
    if (lane == 31) wsum[warp] = v;
    __syncthreads();
    if (warp == 0) {
        int w = wsum[lane], wi = w;
#pragma unroll
        for (int d = 1; d < 32; d <<= 1) {
            int o = __shfl_up_sync(0xFFFFFFFFu, wi, d);
            if (lane >= d) wi += o;
        }
        wsum[lane] = wi - w;
    }
    __syncthreads();
    int C = wsum[warp] + (v - ssum);

    // ---- precision values + chunk max ----
    float mx = 0.0f;
    for (int p = st; p < en; ++p) {
        C += s_c[p];
        if (p < T) {
            float pr = (float)(p + 1) / (float)C;
            prec[p] = pr;
            mx = fmaxf(mx, pr);
        }
    }

    // ---- exclusive suffix-max over chunks (reversed exclusive max-scan) ----
    s_suf[1023 - tid] = mx;
    __syncthreads();
    float a = s_suf[tid], ai = a;
#pragma unroll
    for (int d = 1; d < 32; d <<= 1) {
        float o = __shfl_up_sync(0xFFFFFFFFu, ai, d);
        if (lane >= d) ai = fmaxf(ai, o);
    }
    float le = __shfl_up_sync(0xFFFFFFFFu, ai, 1);
    if (lane == 0) le = 0.0f;
    if (lane == 31) wmax[warp] = ai;
    __syncthreads();
    if (warp == 0) {
        float w0 = wmax[lane], wi = w0;
#pragma unroll
        for (int d = 1; d < 32; d <<= 1) {
            float o = __shfl_up_sync(0xFFFFFFFFu, wi, d);
            if (lane >= d) wi = fmaxf(wi, o);
        }
        float e = __shfl_up_sync(0xFFFFFFFFu, wi, 1);
        if (lane == 0) e = 0.0f;
        wmax[lane] = e;
        if (lane == 31) s_gmax = wi;                      // global max precision
    }
    __syncthreads();
    float suf_excl = fmaxf(wmax[warp], le);
    s_suf[tid] = suf_excl;
    __syncthreads();
    float run = s_suf[1023 - tid];
    __syncthreads();

    // ---- weighted sum (descending within chunk, running suffix max) ----
    double s = 0.0;
    int hi = min(en, T);
    for (int p = hi - 1; p >= st; --p) {
        run = fmaxf(run, prec[p]);
        s += (double)run;
    }

    // ---- double reduction ----
#pragma unroll
    for (int d = 16; d; d >>= 1) s += __shfl_down_sync(0xFFFFFFFFu, s, d);
    if (lane == 0) wdbl[warp] = s;
    __syncthreads();
    if (warp == 0) {
        double t = wdbl[lane];
#pragma unroll
        for (int d = 16; d; d >>= 1) t += __shfl_down_sync(0xFFFFFFFFu, t, d);
        if (lane == 0) {
            if (s_c[0] == 1) t -= (double)s_gmax;         // rank-0 TP excluded
            out[z] = (float)(t / (double)(BB * GG));
            g_T[z] = 0;                                   // restore invariant for replay
        }
    }
}

// ----------------------------------------------------------------------------
// Launcher (graph-capturable: kernels only, default stream)
// ----------------------------------------------------------------------------
extern "C" void kernel_launch(void* const* d_in, const int* in_sizes, int n_in,
                              void* d_out, int out_size) {
    const float*  scores = (const float*)d_in[0];
    const float2* segs   = (const float2*)d_in[1];
    const float2* gts    = (const float2*)d_in[2];
    float* out = (float*)d_out;

    const int smem_greedy = 2 * GG * NW * 4;                       // 50,000 B
    const int smem_sort   = (2 * NBKT + 4) * 4 + TMAX * 8;         // 135,184 B
    const int smem_hist   = (NBKT + 2) * 4 + TMAX * 8;             // 118,792 B
    const int smem_final  = (TMAX + 4 + TMAX) * 4;                 // 102,416 B

    cudaFuncSetAttribute(k_greedy, cudaFuncAttributeMaxDynamicSharedMemorySize, smem_greedy);
    cudaFuncSetAttribute(k_sort,   cudaFuncAttributeMaxDynamicSharedMemorySize, smem_sort);
    cudaFuncSetAttribute(k_hist,   cudaFuncAttributeMaxDynamicSharedMemorySize, smem_hist);
    cudaFuncSetAttribute(k_final,  cudaFuncAttributeMaxDynamicSharedMemorySize, smem_final);

    k_greedy<<<BB, 512, smem_greedy>>>(segs, gts, scores);
    k_sort<<<2, 1024, smem_sort>>>();
    k_hist<<<dim3(148, 2), 1024, smem_hist>>>(scores);
    k_final<<<2, 1024, smem_final>>>(out);
}